// round 14
// baseline (speedup 1.0000x reference)
#include <cuda_runtime.h>
#include <cuda_bf16.h>
#include <cstdint>

// ---------------------------------------------------------------------------
// W8A8 dynamic-quant linear:  y = (q8(x) @ W^T) * act_scale * w_scale + bias
// TOK=4096, K=4096, OUT(N)=12288
//
// Round 14 (on top of round-13 winner: XOR swizzle, 2 CTAs/SM, 128x128 tile):
//  1. Grid order swapped (x=M, y=N): resident wave = 3 N-columns x 32 M-tiles
//     -> ~36 MB working set, L2-resident; A stays hot all waves.
//  2. ks0 fragment ldsm issued BEFORE the cp.async burst each chunk
//     (asm volatile order == SASS order), copies split after ks0/ks1 to
//     de-burst smem writes against ldsm reads.
// ---------------------------------------------------------------------------

#define TOK   4096
#define KDIM  4096
#define NDIM  12288

#define TILE_M 128
#define TILE_N 128
#define NCH    64                // 128-B (64-elem) bf16 K-chunks
#define KCB    128
#define NSTAGE 3

#define ROWB   128               // XOR swizzle, no pad
#define A_BYTES (TILE_M * ROWB)  // 16384
#define B_BYTES (TILE_N * ROWB)  // 16384
#define STAGE_BYTES (A_BYTES + B_BYTES)   // 32768

// SMEM layout (bytes)
#define SM_WS 0                  // 128 floats
#define SM_BS 512                // 128 floats
#define SM_AB 2048
#define SMEM_TOTAL (SM_AB + NSTAGE * STAGE_BYTES)   // 100352  (2 CTAs/SM)

#define W_ELEMS ((size_t)NDIM * KDIM)

// Scratch (module globals -- allocation-free per harness rules)
__device__ __nv_bfloat16 g_xbf[(size_t)TOK * KDIM];
__device__ __nv_bfloat16 g_wbf[W_ELEMS];
__device__ float         g_ascale[TOK];
__device__ int           g_wmode;   // 0=int8 raw, 1=int32, 2=bf16, 3=f32

// ---------------------------------------------------------------------------
__device__ __forceinline__ uint32_t smem_u32(const void* p) {
    uint32_t a;
    asm("{ .reg .u64 t; cvta.to.shared.u64 t, %1; cvt.u32.u64 %0, t; }" : "=r"(a) : "l"(p));
    return a;
}

__device__ __forceinline__ void cp16(uint32_t dst, const void* src) {
    asm volatile("cp.async.cg.shared.global [%0], [%1], 16;" :: "r"(dst), "l"(src));
}

__device__ __forceinline__ void ldsm_x4(uint32_t* r, uint32_t addr) {
    asm volatile("ldmatrix.sync.aligned.m8n8.x4.shared.b16 {%0,%1,%2,%3}, [%4];"
                 : "=r"(r[0]), "=r"(r[1]), "=r"(r[2]), "=r"(r[3]) : "r"(addr));
}

__device__ __forceinline__ void mma_bf16_k16(float* c, const uint32_t* a, uint32_t b0, uint32_t b1) {
    asm volatile(
        "mma.sync.aligned.m16n8k16.row.col.f32.bf16.bf16.f32 "
        "{%0,%1,%2,%3}, {%4,%5,%6,%7}, {%8,%9}, {%0,%1,%2,%3};"
        : "+f"(c[0]), "+f"(c[1]), "+f"(c[2]), "+f"(c[3])
        : "r"(a[0]), "r"(a[1]), "r"(a[2]), "r"(a[3]), "r"(b0), "r"(b1));
}

// ---------------------------------------------------------------------------
// Weight format autodetect + direct-to-bf16 pack (proven rounds 4/7)
// ---------------------------------------------------------------------------
__global__ void detect_kernel(const void* w) {
    __shared__ int ok32, okf32, okbf;
    int tid = threadIdx.x;
    if (tid == 0) { ok32 = 1; okf32 = 1; okbf = 1; }
    __syncthreads();
    const int*            wi = (const int*)w;
    const float*          wf = (const float*)w;
    const __nv_bfloat16*  wb = (const __nv_bfloat16*)w;
#pragma unroll
    for (int i = 0; i < 4; i++) {
        int idx = tid * 4 + i;
        int v = wi[idx];
        if (v < -128 || v > 127) ok32 = 0;
        float f = wf[idx];
        if (!(f == rintf(f)) || f < -128.0f || f > 127.0f) okf32 = 0;
        float b = __bfloat162float(wb[idx]);
        if (!(b == rintf(b)) || b < -128.0f || b > 127.0f) okbf = 0;
    }
    __syncthreads();
    if (tid == 0)
        g_wmode = ok32 ? 1 : (okf32 ? 3 : (okbf ? 2 : 0));
}

__global__ void __launch_bounds__(256) pack_kernel(const void* w) {
    size_t g = (size_t)blockIdx.x * blockDim.x + threadIdx.x;
    if (g * 16 >= W_ELEMS) return;
    int mode = g_wmode;
    float f[16];
    if (mode == 0) {
        int8_t b[16];
        *(int4*)b = ((const int4*)w)[g];
#pragma unroll
        for (int j = 0; j < 16; j++) f[j] = (float)b[j];
    } else if (mode == 1) {
        const int4* wi = (const int4*)w + g * 4;
#pragma unroll
        for (int j = 0; j < 4; j++) {
            int4 v = wi[j];
            f[j * 4 + 0] = (float)(int8_t)v.x; f[j * 4 + 1] = (float)(int8_t)v.y;
            f[j * 4 + 2] = (float)(int8_t)v.z; f[j * 4 + 3] = (float)(int8_t)v.w;
        }
    } else if (mode == 2) {
        const __nv_bfloat16* wb = (const __nv_bfloat16*)w + g * 16;
#pragma unroll
        for (int j = 0; j < 16; j++) f[j] = __bfloat162float(wb[j]);
    } else {
        const float4* wf = (const float4*)w + g * 4;
#pragma unroll
        for (int j = 0; j < 4; j++) {
            float4 v = wf[j];
            f[j * 4 + 0] = v.x; f[j * 4 + 1] = v.y;
            f[j * 4 + 2] = v.z; f[j * 4 + 3] = v.w;
        }
    }
    uint32_t o[8];
#pragma unroll
    for (int j = 0; j < 8; j++) {
        __nv_bfloat162 h = __floats2bfloat162_rn(f[2 * j], f[2 * j + 1]);
        o[j] = *(uint32_t*)&h;
    }
    uint4* dst = (uint4*)(g_wbf + g * 16);
    dst[0] = make_uint4(o[0], o[1], o[2], o[3]);
    dst[1] = make_uint4(o[4], o[5], o[6], o[7]);
}

// ---------------------------------------------------------------------------
// Kernel 1: per-token dynamic quantization -> bf16 (int-valued)
// ---------------------------------------------------------------------------
__device__ __forceinline__ float q8f(float x, float s) {
    float r = rintf(__fdiv_rn(x, s));
    return fminf(fmaxf(r, -128.0f), 127.0f);
}

__global__ void __launch_bounds__(256) quant_kernel(const float* __restrict__ x) {
    int t = blockIdx.x;
    int tid = threadIdx.x;
    const float4* xr = (const float4*)(x + (size_t)t * KDIM);
    float4 v[4];
    float am = 0.0f;
#pragma unroll
    for (int i = 0; i < 4; i++) {
        v[i] = xr[tid * 4 + i];
        am = fmaxf(am, fmaxf(fmaxf(fabsf(v[i].x), fabsf(v[i].y)),
                             fmaxf(fabsf(v[i].z), fabsf(v[i].w))));
    }
    __shared__ float red[256];
    red[tid] = am;
    __syncthreads();
    for (int s = 128; s > 0; s >>= 1) {
        if (tid < s) red[tid] = fmaxf(red[tid], red[tid + s]);
        __syncthreads();
    }
    float s = fmaxf(__fdiv_rn(red[0], 127.0f), 1e-8f);
    if (tid == 0) g_ascale[t] = s;

    float q[16];
    q[0] = q8f(v[0].x, s);  q[1] = q8f(v[0].y, s);  q[2] = q8f(v[0].z, s);  q[3] = q8f(v[0].w, s);
    q[4] = q8f(v[1].x, s);  q[5] = q8f(v[1].y, s);  q[6] = q8f(v[1].z, s);  q[7] = q8f(v[1].w, s);
    q[8] = q8f(v[2].x, s);  q[9] = q8f(v[2].y, s);  q[10] = q8f(v[2].z, s); q[11] = q8f(v[2].w, s);
    q[12] = q8f(v[3].x, s); q[13] = q8f(v[3].y, s); q[14] = q8f(v[3].z, s); q[15] = q8f(v[3].w, s);

    uint32_t h[8];
#pragma unroll
    for (int j = 0; j < 8; j++) {
        __nv_bfloat162 hb = __floats2bfloat162_rn(q[2 * j], q[2 * j + 1]);
        h[j] = *(uint32_t*)&hb;
    }
    uint4* dst = (uint4*)(g_xbf + (size_t)t * KDIM + tid * 16);
    dst[0] = make_uint4(h[0], h[1], h[2], h[3]);
    dst[1] = make_uint4(h[4], h[5], h[6], h[7]);
}

// ---------------------------------------------------------------------------
// GEMM: bf16 HMMA, 128x128 tile, 256 thr (8 warps x 32x64), 3-stage,
// XOR-swizzled smem, 2 CTAs/SM, de-burst copies
// ---------------------------------------------------------------------------
__device__ __forceinline__ void copy_half(const __nv_bfloat16* abase_g,
                                          const __nv_bfloat16* bbase_g,
                                          int c, int stage, int half,
                                          uint32_t sb, int tid) {
    uint32_t st = sb + SM_AB + stage * STAGE_BYTES;
    if (half == 0) {
        // A: 128 rows x 128 B = 1024 cp16 -> 4 per thread
        const char* asrc = (const char*)abase_g + (size_t)c * KCB;
#pragma unroll
        for (int i = 0; i < 4; i++) {
            int idx = tid + i * 256;
            int row = idx >> 3, u = idx & 7;
            cp16(st + row * ROWB + ((u ^ (row & 7)) * 16),
                 asrc + (size_t)row * (KDIM * 2) + u * 16);
        }
    } else {
        // B: 128 rows x 128 B = 1024 cp16 -> 4 per thread
        const char* bsrc = (const char*)bbase_g + (size_t)c * KCB;
        uint32_t bb = st + A_BYTES;
#pragma unroll
        for (int i = 0; i < 4; i++) {
            int idx = tid + i * 256;
            int row = idx >> 3, u = idx & 7;
            cp16(bb + row * ROWB + ((u ^ (row & 7)) * 16),
                 bsrc + (size_t)row * (KDIM * 2) + u * 16);
        }
    }
}

__global__ void __launch_bounds__(256, 2) hmma_gemm(const float* __restrict__ wscale,
                                                    const float* __restrict__ bias,
                                                    float* __restrict__ out) {
    extern __shared__ char smem[];
    uint32_t sb = smem_u32(smem);
    int tid = threadIdx.x, wid = tid >> 5, lane = tid & 31;
    int m0 = blockIdx.x * TILE_M;      // grid swapped: x = M (L2 locality)
    int n0 = blockIdx.y * TILE_N;
    int wm = wid & 3;
    int wn = wid >> 2;

    float* smem_ws = (float*)(smem + SM_WS);
    float* smem_bs = (float*)(smem + SM_BS);
    if (tid < 128)      smem_ws[tid] = wscale[n0 + tid];
    else                smem_bs[tid - 128] = bias[n0 + tid - 128];

    int g = lane >> 3, lr = lane & 7;
    uint32_t arow = (uint32_t)(wm * 32 + (g & 1) * 8 + lr);
    uint32_t aoff = arow * ROWB ^ ((arow & 7) * 16) ^ ((uint32_t)(g >> 1) * 16);
    uint32_t brow = (uint32_t)(wn * 64 + (g >> 1) * 8 + lr);
    uint32_t boff = (uint32_t)A_BYTES + (brow * ROWB ^ ((brow & 7) * 16) ^ ((uint32_t)(g & 1) * 16));

    float acc[2][8][4];
#pragma unroll
    for (int f = 0; f < 2; f++)
#pragma unroll
        for (int nf = 0; nf < 8; nf++)
#pragma unroll
            for (int i = 0; i < 4; i++) acc[f][nf][i] = 0.0f;

    const __nv_bfloat16* Ag = g_xbf + (size_t)m0 * KDIM;
    const __nv_bfloat16* Bg = g_wbf + (size_t)n0 * KDIM;

    copy_half(Ag, Bg, 0, 0, 0, sb, tid);
    copy_half(Ag, Bg, 0, 0, 1, sb, tid);
    asm volatile("cp.async.commit_group;" ::: "memory");
    copy_half(Ag, Bg, 1, 1, 0, sb, tid);
    copy_half(Ag, Bg, 1, 1, 1, sb, tid);
    asm volatile("cp.async.commit_group;" ::: "memory");

    for (int c = 0; c < NCH; c++) {
        if (c < NCH - 1) asm volatile("cp.async.wait_group 1;" ::: "memory");
        else             asm volatile("cp.async.wait_group 0;" ::: "memory");
        __syncthreads();

        uint32_t st = sb + SM_AB + (c % NSTAGE) * STAGE_BYTES;
        bool pre = (c + 2 < NCH);
        int pstage = (c + 2) % NSTAGE;

        // ---- ks0: fragment loads FIRST, then copy bursts interleaved ----
        uint32_t a[2][4], b[4][4];
#pragma unroll
        for (int f = 0; f < 2; f++)
            ldsm_x4(a[f], st + f * (16 * ROWB) + aoff);
#pragma unroll
        for (int q = 0; q < 4; q++)
            ldsm_x4(b[q], st + q * (16 * ROWB) + boff);
        if (pre) copy_half(Ag, Bg, c + 2, pstage, 0, sb, tid);
#pragma unroll
        for (int f = 0; f < 2; f++)
#pragma unroll
            for (int q = 0; q < 4; q++) {
                mma_bf16_k16(acc[f][2 * q],     a[f], b[q][0], b[q][1]);
                mma_bf16_k16(acc[f][2 * q + 1], a[f], b[q][2], b[q][3]);
            }
        if (pre) {
            copy_half(Ag, Bg, c + 2, pstage, 1, sb, tid);
            asm volatile("cp.async.commit_group;" ::: "memory");
        }

        // ---- ks1..3 ----
#pragma unroll
        for (int ks = 1; ks < 4; ks++) {
            uint32_t kpart = (uint32_t)(ks * 32);
#pragma unroll
            for (int f = 0; f < 2; f++)
                ldsm_x4(a[f], st + f * (16 * ROWB) + (aoff ^ kpart));
#pragma unroll
            for (int q = 0; q < 4; q++)
                ldsm_x4(b[q], st + q * (16 * ROWB) + (boff ^ kpart));
#pragma unroll
            for (int f = 0; f < 2; f++)
#pragma unroll
                for (int q = 0; q < 4; q++) {
                    mma_bf16_k16(acc[f][2 * q],     a[f], b[q][0], b[q][1]);
                    mma_bf16_k16(acc[f][2 * q + 1], a[f], b[q][2], b[q][3]);
                }
        }
    }

    int lrow = lane >> 2, lcol2 = (lane & 3) * 2;
#pragma unroll
    for (int f = 0; f < 2; f++) {
        int mA = m0 + wm * 32 + f * 16 + lrow;
        float as0 = g_ascale[mA];
        float as1 = g_ascale[mA + 8];
#pragma unroll
        for (int nf = 0; nf < 8; nf++) {
            int col = wn * 64 + nf * 8 + lcol2;
            float ws0 = smem_ws[col], ws1 = smem_ws[col + 1];
            float bs0 = smem_bs[col], bs1 = smem_bs[col + 1];
            float2 v0, v1;
            v0.x = fmaf(acc[f][nf][0] * as0, ws0, bs0);
            v0.y = fmaf(acc[f][nf][1] * as0, ws1, bs1);
            v1.x = fmaf(acc[f][nf][2] * as1, ws0, bs0);
            v1.y = fmaf(acc[f][nf][3] * as1, ws1, bs1);
            *(float2*)(out + (size_t)mA * NDIM + n0 + col) = v0;
            *(float2*)(out + (size_t)(mA + 8) * NDIM + n0 + col) = v1;
        }
    }
}

// ---------------------------------------------------------------------------
extern "C" void kernel_launch(void* const* d_in, const int* in_sizes, int n_in,
                              void* d_out, int out_size) {
    const float* x;
    const float* bs;
    if (in_sizes[0] == NDIM) {           // alphabetical: bias first
        bs = (const float*)d_in[0];
        x  = (const float*)d_in[3];
    } else {                             // dict order: x first
        x  = (const float*)d_in[0];
        bs = (const float*)d_in[3];
    }
    const void*  w  = d_in[1];
    const float* ws = (const float*)d_in[2];
    float* out = (float*)d_out;

    cudaFuncSetAttribute(hmma_gemm, cudaFuncAttributeMaxDynamicSharedMemorySize, SMEM_TOTAL);

    detect_kernel<<<1, 256>>>(w);
    pack_kernel<<<(int)((W_ELEMS / 16 + 255) / 256), 256>>>(w);
    quant_kernel<<<TOK, 256>>>(x);
    dim3 grid(TOK / TILE_M, NDIM / TILE_N);   // (32, 96) -- x=M for L2 reuse
    hmma_gemm<<<grid, 256, SMEM_TOTAL>>>(ws, bs, out);
}

// round 15
// speedup vs baseline: 1.0946x; 1.0946x over previous
#include <cuda_runtime.h>
#include <cuda_bf16.h>
#include <cstdint>

// ---------------------------------------------------------------------------
// W8A8 dynamic-quant linear:  y = (q8(x) @ W^T) * act_scale * w_scale + bias
// TOK=4096, K=4096, OUT(N)=12288
//
// Round 15: tensor pinned ~75% with 2 CTAs/SM; all intra-CTA scheduling
// changes neutral -> residual idle = coincident per-CTA phase stalls.
// Quadruple streams: 4 CTAs/SM. Tile 128x64, 128 thr, 4 warps of the proven
// 32x64 fragment config (128 regs; 4x128x128 = full RF). 2-stage pipeline,
// XOR swizzle, R8-proven order (wait 0 -> sync -> copy c+1 -> compute c).
// ---------------------------------------------------------------------------

#define TOK   4096
#define KDIM  4096
#define NDIM  12288

#define TILE_M 128
#define TILE_N 64
#define NCH    64                // 128-B (64-elem) bf16 K-chunks
#define KCB    128
#define NSTAGE 2

#define ROWB   128               // XOR swizzle, no pad
#define A_BYTES (TILE_M * ROWB)  // 16384
#define B_BYTES (TILE_N * ROWB)  // 8192
#define STAGE_BYTES (A_BYTES + B_BYTES)   // 24576

// SMEM layout (bytes)
#define SM_WS 0                  // 64 floats
#define SM_BS 256                // 64 floats
#define SM_AB 1024
#define SMEM_TOTAL (SM_AB + NSTAGE * STAGE_BYTES)   // 50176  (4 CTAs/SM)

#define W_ELEMS ((size_t)NDIM * KDIM)

// Scratch (module globals -- allocation-free per harness rules)
__device__ __nv_bfloat16 g_xbf[(size_t)TOK * KDIM];
__device__ __nv_bfloat16 g_wbf[W_ELEMS];
__device__ float         g_ascale[TOK];
__device__ int           g_wmode;   // 0=int8 raw, 1=int32, 2=bf16, 3=f32

// ---------------------------------------------------------------------------
__device__ __forceinline__ uint32_t smem_u32(const void* p) {
    uint32_t a;
    asm("{ .reg .u64 t; cvta.to.shared.u64 t, %1; cvt.u32.u64 %0, t; }" : "=r"(a) : "l"(p));
    return a;
}

__device__ __forceinline__ void cp16(uint32_t dst, const void* src) {
    asm volatile("cp.async.cg.shared.global [%0], [%1], 16;" :: "r"(dst), "l"(src));
}

__device__ __forceinline__ void ldsm_x4(uint32_t* r, uint32_t addr) {
    asm volatile("ldmatrix.sync.aligned.m8n8.x4.shared.b16 {%0,%1,%2,%3}, [%4];"
                 : "=r"(r[0]), "=r"(r[1]), "=r"(r[2]), "=r"(r[3]) : "r"(addr));
}

__device__ __forceinline__ void mma_bf16_k16(float* c, const uint32_t* a, uint32_t b0, uint32_t b1) {
    asm volatile(
        "mma.sync.aligned.m16n8k16.row.col.f32.bf16.bf16.f32 "
        "{%0,%1,%2,%3}, {%4,%5,%6,%7}, {%8,%9}, {%0,%1,%2,%3};"
        : "+f"(c[0]), "+f"(c[1]), "+f"(c[2]), "+f"(c[3])
        : "r"(a[0]), "r"(a[1]), "r"(a[2]), "r"(a[3]), "r"(b0), "r"(b1));
}

// ---------------------------------------------------------------------------
// Weight format autodetect + direct-to-bf16 pack (proven rounds 4/7)
// ---------------------------------------------------------------------------
__global__ void detect_kernel(const void* w) {
    __shared__ int ok32, okf32, okbf;
    int tid = threadIdx.x;
    if (tid == 0) { ok32 = 1; okf32 = 1; okbf = 1; }
    __syncthreads();
    const int*            wi = (const int*)w;
    const float*          wf = (const float*)w;
    const __nv_bfloat16*  wb = (const __nv_bfloat16*)w;
#pragma unroll
    for (int i = 0; i < 4; i++) {
        int idx = tid * 4 + i;
        int v = wi[idx];
        if (v < -128 || v > 127) ok32 = 0;
        float f = wf[idx];
        if (!(f == rintf(f)) || f < -128.0f || f > 127.0f) okf32 = 0;
        float b = __bfloat162float(wb[idx]);
        if (!(b == rintf(b)) || b < -128.0f || b > 127.0f) okbf = 0;
    }
    __syncthreads();
    if (tid == 0)
        g_wmode = ok32 ? 1 : (okf32 ? 3 : (okbf ? 2 : 0));
}

__global__ void __launch_bounds__(256) pack_kernel(const void* w) {
    size_t g = (size_t)blockIdx.x * blockDim.x + threadIdx.x;
    if (g * 16 >= W_ELEMS) return;
    int mode = g_wmode;
    float f[16];
    if (mode == 0) {
        int8_t b[16];
        *(int4*)b = ((const int4*)w)[g];
#pragma unroll
        for (int j = 0; j < 16; j++) f[j] = (float)b[j];
    } else if (mode == 1) {
        const int4* wi = (const int4*)w + g * 4;
#pragma unroll
        for (int j = 0; j < 4; j++) {
            int4 v = wi[j];
            f[j * 4 + 0] = (float)(int8_t)v.x; f[j * 4 + 1] = (float)(int8_t)v.y;
            f[j * 4 + 2] = (float)(int8_t)v.z; f[j * 4 + 3] = (float)(int8_t)v.w;
        }
    } else if (mode == 2) {
        const __nv_bfloat16* wb = (const __nv_bfloat16*)w + g * 16;
#pragma unroll
        for (int j = 0; j < 16; j++) f[j] = __bfloat162float(wb[j]);
    } else {
        const float4* wf = (const float4*)w + g * 4;
#pragma unroll
        for (int j = 0; j < 4; j++) {
            float4 v = wf[j];
            f[j * 4 + 0] = v.x; f[j * 4 + 1] = v.y;
            f[j * 4 + 2] = v.z; f[j * 4 + 3] = v.w;
        }
    }
    uint32_t o[8];
#pragma unroll
    for (int j = 0; j < 8; j++) {
        __nv_bfloat162 h = __floats2bfloat162_rn(f[2 * j], f[2 * j + 1]);
        o[j] = *(uint32_t*)&h;
    }
    uint4* dst = (uint4*)(g_wbf + g * 16);
    dst[0] = make_uint4(o[0], o[1], o[2], o[3]);
    dst[1] = make_uint4(o[4], o[5], o[6], o[7]);
}

// ---------------------------------------------------------------------------
// Kernel 1: per-token dynamic quantization -> bf16 (int-valued)
// ---------------------------------------------------------------------------
__device__ __forceinline__ float q8f(float x, float s) {
    float r = rintf(__fdiv_rn(x, s));
    return fminf(fmaxf(r, -128.0f), 127.0f);
}

__global__ void __launch_bounds__(256) quant_kernel(const float* __restrict__ x) {
    int t = blockIdx.x;
    int tid = threadIdx.x;
    const float4* xr = (const float4*)(x + (size_t)t * KDIM);
    float4 v[4];
    float am = 0.0f;
#pragma unroll
    for (int i = 0; i < 4; i++) {
        v[i] = xr[tid * 4 + i];
        am = fmaxf(am, fmaxf(fmaxf(fabsf(v[i].x), fabsf(v[i].y)),
                             fmaxf(fabsf(v[i].z), fabsf(v[i].w))));
    }
    __shared__ float red[256];
    red[tid] = am;
    __syncthreads();
    for (int s = 128; s > 0; s >>= 1) {
        if (tid < s) red[tid] = fmaxf(red[tid], red[tid + s]);
        __syncthreads();
    }
    float s = fmaxf(__fdiv_rn(red[0], 127.0f), 1e-8f);
    if (tid == 0) g_ascale[t] = s;

    float q[16];
    q[0] = q8f(v[0].x, s);  q[1] = q8f(v[0].y, s);  q[2] = q8f(v[0].z, s);  q[3] = q8f(v[0].w, s);
    q[4] = q8f(v[1].x, s);  q[5] = q8f(v[1].y, s);  q[6] = q8f(v[1].z, s);  q[7] = q8f(v[1].w, s);
    q[8] = q8f(v[2].x, s);  q[9] = q8f(v[2].y, s);  q[10] = q8f(v[2].z, s); q[11] = q8f(v[2].w, s);
    q[12] = q8f(v[3].x, s); q[13] = q8f(v[3].y, s); q[14] = q8f(v[3].z, s); q[15] = q8f(v[3].w, s);

    uint32_t h[8];
#pragma unroll
    for (int j = 0; j < 8; j++) {
        __nv_bfloat162 hb = __floats2bfloat162_rn(q[2 * j], q[2 * j + 1]);
        h[j] = *(uint32_t*)&hb;
    }
    uint4* dst = (uint4*)(g_xbf + (size_t)t * KDIM + tid * 16);
    dst[0] = make_uint4(h[0], h[1], h[2], h[3]);
    dst[1] = make_uint4(h[4], h[5], h[6], h[7]);
}

// ---------------------------------------------------------------------------
// GEMM: bf16 HMMA, 128x64 tile, 128 thr (4 warps x 32x64), 2-stage,
// XOR-swizzled smem, 4 CTAs/SM
// ---------------------------------------------------------------------------
__device__ __forceinline__ void copy_chunk(const __nv_bfloat16* abase_g,
                                           const __nv_bfloat16* bbase_g,
                                           int c, int stage, uint32_t sb, int tid) {
    uint32_t st = sb + SM_AB + stage * STAGE_BYTES;
    // A: 128 rows x 128 B = 1024 cp16 -> 8 per thread
    const char* asrc = (const char*)abase_g + (size_t)c * KCB;
#pragma unroll
    for (int i = 0; i < 8; i++) {
        int idx = tid + i * 128;
        int row = idx >> 3, u = idx & 7;
        cp16(st + row * ROWB + ((u ^ (row & 7)) * 16),
             asrc + (size_t)row * (KDIM * 2) + u * 16);
    }
    // B: 64 rows x 128 B = 512 cp16 -> 4 per thread
    const char* bsrc = (const char*)bbase_g + (size_t)c * KCB;
    uint32_t bb = st + A_BYTES;
#pragma unroll
    for (int i = 0; i < 4; i++) {
        int idx = tid + i * 128;
        int row = idx >> 3, u = idx & 7;
        cp16(bb + row * ROWB + ((u ^ (row & 7)) * 16),
             bsrc + (size_t)row * (KDIM * 2) + u * 16);
    }
}

__global__ void __launch_bounds__(128, 4) hmma_gemm(const float* __restrict__ wscale,
                                                    const float* __restrict__ bias,
                                                    float* __restrict__ out) {
    extern __shared__ char smem[];
    uint32_t sb = smem_u32(smem);
    int tid = threadIdx.x, wid = tid >> 5, lane = tid & 31;
    int m0 = blockIdx.x * TILE_M;      // x = M (L2 reuse of A across waves)
    int n0 = blockIdx.y * TILE_N;
    int wm = wid;                      // 4 M-strips of 32; warp N-tile = full 64

    float* smem_ws = (float*)(smem + SM_WS);
    float* smem_bs = (float*)(smem + SM_BS);
    if (tid < 64)       smem_ws[tid] = wscale[n0 + tid];
    else                smem_bs[tid - 64] = bias[n0 + tid - 64];

    int g = lane >> 3, lr = lane & 7;
    uint32_t arow = (uint32_t)(wm * 32 + (g & 1) * 8 + lr);
    uint32_t aoff = arow * ROWB ^ ((arow & 7) * 16) ^ ((uint32_t)(g >> 1) * 16);
    uint32_t brow = (uint32_t)((g >> 1) * 8 + lr);
    uint32_t boff = (uint32_t)A_BYTES + (brow * ROWB ^ ((brow & 7) * 16) ^ ((uint32_t)(g & 1) * 16));

    float acc[2][8][4];
#pragma unroll
    for (int f = 0; f < 2; f++)
#pragma unroll
        for (int nf = 0; nf < 8; nf++)
#pragma unroll
            for (int i = 0; i < 4; i++) acc[f][nf][i] = 0.0f;

    const __nv_bfloat16* Ag = g_xbf + (size_t)m0 * KDIM;
    const __nv_bfloat16* Bg = g_wbf + (size_t)n0 * KDIM;

    copy_chunk(Ag, Bg, 0, 0, sb, tid);
    asm volatile("cp.async.commit_group;" ::: "memory");

    for (int c = 0; c < NCH; c++) {
        asm volatile("cp.async.wait_group 0;" ::: "memory");   // own chunk c done
        __syncthreads();          // cross-thread visibility + all warps off c-1
        if (c + 1 < NCH) {
            copy_chunk(Ag, Bg, c + 1, (c + 1) & 1, sb, tid);
            asm volatile("cp.async.commit_group;" ::: "memory");
        }

        uint32_t st = sb + SM_AB + (c & 1) * STAGE_BYTES;
#pragma unroll
        for (int ks = 0; ks < 4; ks++) {      // 4 x k16 (32 B) per 128-B chunk
            uint32_t kpart = (uint32_t)(ks * 32);
            uint32_t a[2][4];
#pragma unroll
            for (int f = 0; f < 2; f++)
                ldsm_x4(a[f], st + f * (16 * ROWB) + (aoff ^ kpart));
            uint32_t b[4][4];
#pragma unroll
            for (int q = 0; q < 4; q++)
                ldsm_x4(b[q], st + q * (16 * ROWB) + (boff ^ kpart));
#pragma unroll
            for (int f = 0; f < 2; f++)
#pragma unroll
                for (int q = 0; q < 4; q++) {
                    mma_bf16_k16(acc[f][2 * q],     a[f], b[q][0], b[q][1]);
                    mma_bf16_k16(acc[f][2 * q + 1], a[f], b[q][2], b[q][3]);
                }
        }
    }

    int lrow = lane >> 2, lcol2 = (lane & 3) * 2;
#pragma unroll
    for (int f = 0; f < 2; f++) {
        int mA = m0 + wm * 32 + f * 16 + lrow;
        float as0 = g_ascale[mA];
        float as1 = g_ascale[mA + 8];
#pragma unroll
        for (int nf = 0; nf < 8; nf++) {
            int col = nf * 8 + lcol2;
            float ws0 = smem_ws[col], ws1 = smem_ws[col + 1];
            float bs0 = smem_bs[col], bs1 = smem_bs[col + 1];
            float2 v0, v1;
            v0.x = fmaf(acc[f][nf][0] * as0, ws0, bs0);
            v0.y = fmaf(acc[f][nf][1] * as0, ws1, bs1);
            v1.x = fmaf(acc[f][nf][2] * as1, ws0, bs0);
            v1.y = fmaf(acc[f][nf][3] * as1, ws1, bs1);
            *(float2*)(out + (size_t)mA * NDIM + n0 + col) = v0;
            *(float2*)(out + (size_t)(mA + 8) * NDIM + n0 + col) = v1;
        }
    }
}

// ---------------------------------------------------------------------------
extern "C" void kernel_launch(void* const* d_in, const int* in_sizes, int n_in,
                              void* d_out, int out_size) {
    const float* x;
    const float* bs;
    if (in_sizes[0] == NDIM) {           // alphabetical: bias first
        bs = (const float*)d_in[0];
        x  = (const float*)d_in[3];
    } else {                             // dict order: x first
        x  = (const float*)d_in[0];
        bs = (const float*)d_in[3];
    }
    const void*  w  = d_in[1];
    const float* ws = (const float*)d_in[2];
    float* out = (float*)d_out;

    cudaFuncSetAttribute(hmma_gemm, cudaFuncAttributeMaxDynamicSharedMemorySize, SMEM_TOTAL);

    detect_kernel<<<1, 256>>>(w);
    pack_kernel<<<(int)((W_ELEMS / 16 + 255) / 256), 256>>>(w);
    quant_kernel<<<TOK, 256>>>(x);
    dim3 grid(TOK / TILE_M, NDIM / TILE_N);   // (32, 192)
    hmma_gemm<<<grid, 128, SMEM_TOTAL>>>(ws, bs, out);
}

// round 16
// speedup vs baseline: 1.1004x; 1.0053x over previous
#include <cuda_runtime.h>
#include <cuda_bf16.h>
#include <cstdint>

// ---------------------------------------------------------------------------
// W8A8 dynamic-quant linear:  y = (q8(x) @ W^T) * act_scale * w_scale + bias
// TOK=4096, K=4096, OUT(N)=12288
//
// Round 16: GEMM = round-15 winner (4 CTAs/SM, 128x64 tile, XOR swizzle,
// 2-stage, tensor 82.5%) UNCHANGED. Prep collapsed from 3 launches to 1:
//  - detect folded into pack blocks (first-1024-elems mode check, L2 bcast)
//  - quant + pack fused in one grid (blocks [0,TOK)=quant, rest=pack) so
//    the two run concurrently instead of serialized.
// ---------------------------------------------------------------------------

#define TOK   4096
#define KDIM  4096
#define NDIM  12288

#define TILE_M 128
#define TILE_N 64
#define NCH    64                // 128-B (64-elem) bf16 K-chunks
#define KCB    128
#define NSTAGE 2

#define ROWB   128               // XOR swizzle, no pad
#define A_BYTES (TILE_M * ROWB)  // 16384
#define B_BYTES (TILE_N * ROWB)  // 8192
#define STAGE_BYTES (A_BYTES + B_BYTES)   // 24576

// SMEM layout (bytes)
#define SM_WS 0                  // 64 floats
#define SM_BS 256                // 64 floats
#define SM_AB 1024
#define SMEM_TOTAL (SM_AB + NSTAGE * STAGE_BYTES)   // 50176  (4 CTAs/SM)

#define W_ELEMS ((size_t)NDIM * KDIM)
#define PACK_GROUPS (W_ELEMS / 16)            // 3145728
#define PACK_BLOCKS ((int)(PACK_GROUPS / 256))  // 12288
#define PREP_GRID (TOK + PACK_BLOCKS)         // 16384

// Scratch (module globals -- allocation-free per harness rules)
__device__ __nv_bfloat16 g_xbf[(size_t)TOK * KDIM];
__device__ __nv_bfloat16 g_wbf[W_ELEMS];
__device__ float         g_ascale[TOK];

// ---------------------------------------------------------------------------
__device__ __forceinline__ uint32_t smem_u32(const void* p) {
    uint32_t a;
    asm("{ .reg .u64 t; cvta.to.shared.u64 t, %1; cvt.u32.u64 %0, t; }" : "=r"(a) : "l"(p));
    return a;
}

__device__ __forceinline__ void cp16(uint32_t dst, const void* src) {
    asm volatile("cp.async.cg.shared.global [%0], [%1], 16;" :: "r"(dst), "l"(src));
}

__device__ __forceinline__ void ldsm_x4(uint32_t* r, uint32_t addr) {
    asm volatile("ldmatrix.sync.aligned.m8n8.x4.shared.b16 {%0,%1,%2,%3}, [%4];"
                 : "=r"(r[0]), "=r"(r[1]), "=r"(r[2]), "=r"(r[3]) : "r"(addr));
}

__device__ __forceinline__ void mma_bf16_k16(float* c, const uint32_t* a, uint32_t b0, uint32_t b1) {
    asm volatile(
        "mma.sync.aligned.m16n8k16.row.col.f32.bf16.bf16.f32 "
        "{%0,%1,%2,%3}, {%4,%5,%6,%7}, {%8,%9}, {%0,%1,%2,%3};"
        : "+f"(c[0]), "+f"(c[1]), "+f"(c[2]), "+f"(c[3])
        : "r"(a[0]), "r"(a[1]), "r"(a[2]), "r"(a[3]), "r"(b0), "r"(b1));
}

// ---------------------------------------------------------------------------
// Fused prep: blocks [0,TOK) quantize one token each; blocks [TOK, ...) pack
// a weight slice to bf16 (mode re-derived per block from first 1024 elems).
// ---------------------------------------------------------------------------
__device__ __forceinline__ float q8f(float x, float s) {
    float r = rintf(__fdiv_rn(x, s));
    return fminf(fmaxf(r, -128.0f), 127.0f);
}

__global__ void __launch_bounds__(256) prep_kernel(const float* __restrict__ x,
                                                   const void* __restrict__ w) {
    int tid = threadIdx.x;

    if (blockIdx.x < TOK) {
        // ---------------- quant path (identical math to proven quant_kernel)
        int t = blockIdx.x;
        const float4* xr = (const float4*)(x + (size_t)t * KDIM);
        float4 v[4];
        float am = 0.0f;
#pragma unroll
        for (int i = 0; i < 4; i++) {
            v[i] = xr[tid * 4 + i];
            am = fmaxf(am, fmaxf(fmaxf(fabsf(v[i].x), fabsf(v[i].y)),
                                 fmaxf(fabsf(v[i].z), fabsf(v[i].w))));
        }
        __shared__ float red[256];
        red[tid] = am;
        __syncthreads();
        for (int s = 128; s > 0; s >>= 1) {
            if (tid < s) red[tid] = fmaxf(red[tid], red[tid + s]);
            __syncthreads();
        }
        float s = fmaxf(__fdiv_rn(red[0], 127.0f), 1e-8f);
        if (tid == 0) g_ascale[t] = s;

        float q[16];
        q[0] = q8f(v[0].x, s);  q[1] = q8f(v[0].y, s);  q[2] = q8f(v[0].z, s);  q[3] = q8f(v[0].w, s);
        q[4] = q8f(v[1].x, s);  q[5] = q8f(v[1].y, s);  q[6] = q8f(v[1].z, s);  q[7] = q8f(v[1].w, s);
        q[8] = q8f(v[2].x, s);  q[9] = q8f(v[2].y, s);  q[10] = q8f(v[2].z, s); q[11] = q8f(v[2].w, s);
        q[12] = q8f(v[3].x, s); q[13] = q8f(v[3].y, s); q[14] = q8f(v[3].z, s); q[15] = q8f(v[3].w, s);

        uint32_t h[8];
#pragma unroll
        for (int j = 0; j < 8; j++) {
            __nv_bfloat162 hb = __floats2bfloat162_rn(q[2 * j], q[2 * j + 1]);
            h[j] = *(uint32_t*)&hb;
        }
        uint4* dst = (uint4*)(g_xbf + (size_t)t * KDIM + tid * 16);
        dst[0] = make_uint4(h[0], h[1], h[2], h[3]);
        dst[1] = make_uint4(h[4], h[5], h[6], h[7]);
    } else {
        // ---------------- pack path with inline mode detection
        __shared__ int ok32, okf32, okbf;
        if (tid == 0) { ok32 = 1; okf32 = 1; okbf = 1; }
        __syncthreads();
        {
            const int*            wi = (const int*)w;
            const float*          wf = (const float*)w;
            const __nv_bfloat16*  wb = (const __nv_bfloat16*)w;
#pragma unroll
            for (int i = 0; i < 4; i++) {
                int idx = tid * 4 + i;           // first 1024 elems, L2-broadcast
                int vv = wi[idx];
                if (vv < -128 || vv > 127) ok32 = 0;
                float ff = wf[idx];
                if (!(ff == rintf(ff)) || ff < -128.0f || ff > 127.0f) okf32 = 0;
                float bb = __bfloat162float(wb[idx]);
                if (!(bb == rintf(bb)) || bb < -128.0f || bb > 127.0f) okbf = 0;
            }
        }
        __syncthreads();
        int mode = ok32 ? 1 : (okf32 ? 3 : (okbf ? 2 : 0));

        size_t g = (size_t)(blockIdx.x - TOK) * 256 + tid;   // group of 16 elems
        float f[16];
        if (mode == 0) {
            int8_t b[16];
            *(int4*)b = ((const int4*)w)[g];
#pragma unroll
            for (int j = 0; j < 16; j++) f[j] = (float)b[j];
        } else if (mode == 1) {
            const int4* wi = (const int4*)w + g * 4;
#pragma unroll
            for (int j = 0; j < 4; j++) {
                int4 v = wi[j];
                f[j * 4 + 0] = (float)(int8_t)v.x; f[j * 4 + 1] = (float)(int8_t)v.y;
                f[j * 4 + 2] = (float)(int8_t)v.z; f[j * 4 + 3] = (float)(int8_t)v.w;
            }
        } else if (mode == 2) {
            const __nv_bfloat16* wb = (const __nv_bfloat16*)w + g * 16;
#pragma unroll
            for (int j = 0; j < 16; j++) f[j] = __bfloat162float(wb[j]);
        } else {
            const float4* wf = (const float4*)w + g * 4;
#pragma unroll
            for (int j = 0; j < 4; j++) {
                float4 v = wf[j];
                f[j * 4 + 0] = v.x; f[j * 4 + 1] = v.y;
                f[j * 4 + 2] = v.z; f[j * 4 + 3] = v.w;
            }
        }
        uint32_t o[8];
#pragma unroll
        for (int j = 0; j < 8; j++) {
            __nv_bfloat162 h = __floats2bfloat162_rn(f[2 * j], f[2 * j + 1]);
            o[j] = *(uint32_t*)&h;
        }
        uint4* dst = (uint4*)(g_wbf + g * 16);
        dst[0] = make_uint4(o[0], o[1], o[2], o[3]);
        dst[1] = make_uint4(o[4], o[5], o[6], o[7]);
    }
}

// ---------------------------------------------------------------------------
// GEMM: bf16 HMMA, 128x64 tile, 128 thr (4 warps x 32x64), 2-stage,
// XOR-swizzled smem, 4 CTAs/SM  (round-15 winner, unchanged)
// ---------------------------------------------------------------------------
__device__ __forceinline__ void copy_chunk(const __nv_bfloat16* abase_g,
                                           const __nv_bfloat16* bbase_g,
                                           int c, int stage, uint32_t sb, int tid) {
    uint32_t st = sb + SM_AB + stage * STAGE_BYTES;
    const char* asrc = (const char*)abase_g + (size_t)c * KCB;
#pragma unroll
    for (int i = 0; i < 8; i++) {
        int idx = tid + i * 128;
        int row = idx >> 3, u = idx & 7;
        cp16(st + row * ROWB + ((u ^ (row & 7)) * 16),
             asrc + (size_t)row * (KDIM * 2) + u * 16);
    }
    const char* bsrc = (const char*)bbase_g + (size_t)c * KCB;
    uint32_t bb = st + A_BYTES;
#pragma unroll
    for (int i = 0; i < 4; i++) {
        int idx = tid + i * 128;
        int row = idx >> 3, u = idx & 7;
        cp16(bb + row * ROWB + ((u ^ (row & 7)) * 16),
             bsrc + (size_t)row * (KDIM * 2) + u * 16);
    }
}

__global__ void __launch_bounds__(128, 4) hmma_gemm(const float* __restrict__ wscale,
                                                    const float* __restrict__ bias,
                                                    float* __restrict__ out) {
    extern __shared__ char smem[];
    uint32_t sb = smem_u32(smem);
    int tid = threadIdx.x, wid = tid >> 5, lane = tid & 31;
    int m0 = blockIdx.x * TILE_M;
    int n0 = blockIdx.y * TILE_N;
    int wm = wid;

    float* smem_ws = (float*)(smem + SM_WS);
    float* smem_bs = (float*)(smem + SM_BS);
    if (tid < 64)       smem_ws[tid] = wscale[n0 + tid];
    else                smem_bs[tid - 64] = bias[n0 + tid - 64];

    int g = lane >> 3, lr = lane & 7;
    uint32_t arow = (uint32_t)(wm * 32 + (g & 1) * 8 + lr);
    uint32_t aoff = arow * ROWB ^ ((arow & 7) * 16) ^ ((uint32_t)(g >> 1) * 16);
    uint32_t brow = (uint32_t)((g >> 1) * 8 + lr);
    uint32_t boff = (uint32_t)A_BYTES + (brow * ROWB ^ ((brow & 7) * 16) ^ ((uint32_t)(g & 1) * 16));

    float acc[2][8][4];
#pragma unroll
    for (int f = 0; f < 2; f++)
#pragma unroll
        for (int nf = 0; nf < 8; nf++)
#pragma unroll
            for (int i = 0; i < 4; i++) acc[f][nf][i] = 0.0f;

    const __nv_bfloat16* Ag = g_xbf + (size_t)m0 * KDIM;
    const __nv_bfloat16* Bg = g_wbf + (size_t)n0 * KDIM;

    copy_chunk(Ag, Bg, 0, 0, sb, tid);
    asm volatile("cp.async.commit_group;" ::: "memory");

    for (int c = 0; c < NCH; c++) {
        asm volatile("cp.async.wait_group 0;" ::: "memory");
        __syncthreads();
        if (c + 1 < NCH) {
            copy_chunk(Ag, Bg, c + 1, (c + 1) & 1, sb, tid);
            asm volatile("cp.async.commit_group;" ::: "memory");
        }

        uint32_t st = sb + SM_AB + (c & 1) * STAGE_BYTES;
#pragma unroll
        for (int ks = 0; ks < 4; ks++) {
            uint32_t kpart = (uint32_t)(ks * 32);
            uint32_t a[2][4];
#pragma unroll
            for (int f = 0; f < 2; f++)
                ldsm_x4(a[f], st + f * (16 * ROWB) + (aoff ^ kpart));
            uint32_t b[4][4];
#pragma unroll
            for (int q = 0; q < 4; q++)
                ldsm_x4(b[q], st + q * (16 * ROWB) + (boff ^ kpart));
#pragma unroll
            for (int f = 0; f < 2; f++)
#pragma unroll
                for (int q = 0; q < 4; q++) {
                    mma_bf16_k16(acc[f][2 * q],     a[f], b[q][0], b[q][1]);
                    mma_bf16_k16(acc[f][2 * q + 1], a[f], b[q][2], b[q][3]);
                }
        }
    }

    int lrow = lane >> 2, lcol2 = (lane & 3) * 2;
#pragma unroll
    for (int f = 0; f < 2; f++) {
        int mA = m0 + wm * 32 + f * 16 + lrow;
        float as0 = g_ascale[mA];
        float as1 = g_ascale[mA + 8];
#pragma unroll
        for (int nf = 0; nf < 8; nf++) {
            int col = nf * 8 + lcol2;
            float ws0 = smem_ws[col], ws1 = smem_ws[col + 1];
            float bs0 = smem_bs[col], bs1 = smem_bs[col + 1];
            float2 v0, v1;
            v0.x = fmaf(acc[f][nf][0] * as0, ws0, bs0);
            v0.y = fmaf(acc[f][nf][1] * as0, ws1, bs1);
            v1.x = fmaf(acc[f][nf][2] * as1, ws0, bs0);
            v1.y = fmaf(acc[f][nf][3] * as1, ws1, bs1);
            *(float2*)(out + (size_t)mA * NDIM + n0 + col) = v0;
            *(float2*)(out + (size_t)(mA + 8) * NDIM + n0 + col) = v1;
        }
    }
}

// ---------------------------------------------------------------------------
extern "C" void kernel_launch(void* const* d_in, const int* in_sizes, int n_in,
                              void* d_out, int out_size) {
    const float* x;
    const float* bs;
    if (in_sizes[0] == NDIM) {           // alphabetical: bias first
        bs = (const float*)d_in[0];
        x  = (const float*)d_in[3];
    } else {                             // dict order: x first
        x  = (const float*)d_in[0];
        bs = (const float*)d_in[3];
    }
    const void*  w  = d_in[1];
    const float* ws = (const float*)d_in[2];
    float* out = (float*)d_out;

    cudaFuncSetAttribute(hmma_gemm, cudaFuncAttributeMaxDynamicSharedMemorySize, SMEM_TOTAL);

    prep_kernel<<<PREP_GRID, 256>>>(x, w);     // quant (4096) + pack (12288) fused
    dim3 grid(TOK / TILE_M, NDIM / TILE_N);    // (32, 192)
    hmma_gemm<<<grid, 128, SMEM_TOTAL>>>(ws, bs, out);
}

// round 17
// speedup vs baseline: 1.1138x; 1.0122x over previous
#include <cuda_runtime.h>
#include <cuda_bf16.h>
#include <cstdint>

// ---------------------------------------------------------------------------
// W8A8 dynamic-quant linear:  y = (q8(x) @ W^T) * act_scale * w_scale + bias
// TOK=4096, K=4096, OUT(N)=12288
//
// Round 17: L1 (68%) is the co-binder -- ldsm 2x amplification at 32x64 warp
// tiles. Combine the two proven halves: R8's 64x64 warp tile (0.25 ldsm/MMA,
// 226 regs, verified) + R15's 4 CTA streams. 64-thread CTAs (2 warps) make
// 226 regs legal at 4 CTAs/SM (2 warps/SMSP x 226 x 32 = 14.5K <= 16K RF).
// Prep (fused quant+pack) unchanged from round 16.
// ---------------------------------------------------------------------------

#define TOK   4096
#define KDIM  4096
#define NDIM  12288

#define TILE_M 128
#define TILE_N 64
#define NCH    64                // 128-B (64-elem) bf16 K-chunks
#define KCB    128
#define NSTAGE 2

#define ROWB   128               // XOR swizzle, no pad
#define A_BYTES (TILE_M * ROWB)  // 16384
#define B_BYTES (TILE_N * ROWB)  // 8192
#define STAGE_BYTES (A_BYTES + B_BYTES)   // 24576

// SMEM layout (bytes)
#define SM_WS 0                  // 64 floats
#define SM_BS 256                // 64 floats
#define SM_AB 1024
#define SMEM_TOTAL (SM_AB + NSTAGE * STAGE_BYTES)   // 50176  (4 CTAs/SM)

#define W_ELEMS ((size_t)NDIM * KDIM)
#define PACK_GROUPS (W_ELEMS / 16)
#define PACK_BLOCKS ((int)(PACK_GROUPS / 256))  // 12288
#define PREP_GRID (TOK + PACK_BLOCKS)           // 16384

// Scratch (module globals -- allocation-free per harness rules)
__device__ __nv_bfloat16 g_xbf[(size_t)TOK * KDIM];
__device__ __nv_bfloat16 g_wbf[W_ELEMS];
__device__ float         g_ascale[TOK];

// ---------------------------------------------------------------------------
__device__ __forceinline__ uint32_t smem_u32(const void* p) {
    uint32_t a;
    asm("{ .reg .u64 t; cvta.to.shared.u64 t, %1; cvt.u32.u64 %0, t; }" : "=r"(a) : "l"(p));
    return a;
}

__device__ __forceinline__ void cp16(uint32_t dst, const void* src) {
    asm volatile("cp.async.cg.shared.global [%0], [%1], 16;" :: "r"(dst), "l"(src));
}

__device__ __forceinline__ void ldsm_x4(uint32_t* r, uint32_t addr) {
    asm volatile("ldmatrix.sync.aligned.m8n8.x4.shared.b16 {%0,%1,%2,%3}, [%4];"
                 : "=r"(r[0]), "=r"(r[1]), "=r"(r[2]), "=r"(r[3]) : "r"(addr));
}

__device__ __forceinline__ void mma_bf16_k16(float* c, const uint32_t* a, uint32_t b0, uint32_t b1) {
    asm volatile(
        "mma.sync.aligned.m16n8k16.row.col.f32.bf16.bf16.f32 "
        "{%0,%1,%2,%3}, {%4,%5,%6,%7}, {%8,%9}, {%0,%1,%2,%3};"
        : "+f"(c[0]), "+f"(c[1]), "+f"(c[2]), "+f"(c[3])
        : "r"(a[0]), "r"(a[1]), "r"(a[2]), "r"(a[3]), "r"(b0), "r"(b1));
}

// ---------------------------------------------------------------------------
// Fused prep (unchanged from round 16): blocks [0,TOK) quantize one token;
// blocks [TOK,...) pack a weight slice to bf16 (mode re-derived per block).
// ---------------------------------------------------------------------------
__device__ __forceinline__ float q8f(float x, float s) {
    float r = rintf(__fdiv_rn(x, s));
    return fminf(fmaxf(r, -128.0f), 127.0f);
}

__global__ void __launch_bounds__(256) prep_kernel(const float* __restrict__ x,
                                                   const void* __restrict__ w) {
    int tid = threadIdx.x;

    if (blockIdx.x < TOK) {
        int t = blockIdx.x;
        const float4* xr = (const float4*)(x + (size_t)t * KDIM);
        float4 v[4];
        float am = 0.0f;
#pragma unroll
        for (int i = 0; i < 4; i++) {
            v[i] = xr[tid * 4 + i];
            am = fmaxf(am, fmaxf(fmaxf(fabsf(v[i].x), fabsf(v[i].y)),
                                 fmaxf(fabsf(v[i].z), fabsf(v[i].w))));
        }
        __shared__ float red[256];
        red[tid] = am;
        __syncthreads();
        for (int s = 128; s > 0; s >>= 1) {
            if (tid < s) red[tid] = fmaxf(red[tid], red[tid + s]);
            __syncthreads();
        }
        float s = fmaxf(__fdiv_rn(red[0], 127.0f), 1e-8f);
        if (tid == 0) g_ascale[t] = s;

        float q[16];
        q[0] = q8f(v[0].x, s);  q[1] = q8f(v[0].y, s);  q[2] = q8f(v[0].z, s);  q[3] = q8f(v[0].w, s);
        q[4] = q8f(v[1].x, s);  q[5] = q8f(v[1].y, s);  q[6] = q8f(v[1].z, s);  q[7] = q8f(v[1].w, s);
        q[8] = q8f(v[2].x, s);  q[9] = q8f(v[2].y, s);  q[10] = q8f(v[2].z, s); q[11] = q8f(v[2].w, s);
        q[12] = q8f(v[3].x, s); q[13] = q8f(v[3].y, s); q[14] = q8f(v[3].z, s); q[15] = q8f(v[3].w, s);

        uint32_t h[8];
#pragma unroll
        for (int j = 0; j < 8; j++) {
            __nv_bfloat162 hb = __floats2bfloat162_rn(q[2 * j], q[2 * j + 1]);
            h[j] = *(uint32_t*)&hb;
        }
        uint4* dst = (uint4*)(g_xbf + (size_t)t * KDIM + tid * 16);
        dst[0] = make_uint4(h[0], h[1], h[2], h[3]);
        dst[1] = make_uint4(h[4], h[5], h[6], h[7]);
    } else {
        __shared__ int ok32, okf32, okbf;
        if (tid == 0) { ok32 = 1; okf32 = 1; okbf = 1; }
        __syncthreads();
        {
            const int*            wi = (const int*)w;
            const float*          wf = (const float*)w;
            const __nv_bfloat16*  wb = (const __nv_bfloat16*)w;
#pragma unroll
            for (int i = 0; i < 4; i++) {
                int idx = tid * 4 + i;
                int vv = wi[idx];
                if (vv < -128 || vv > 127) ok32 = 0;
                float ff = wf[idx];
                if (!(ff == rintf(ff)) || ff < -128.0f || ff > 127.0f) okf32 = 0;
                float bb = __bfloat162float(wb[idx]);
                if (!(bb == rintf(bb)) || bb < -128.0f || bb > 127.0f) okbf = 0;
            }
        }
        __syncthreads();
        int mode = ok32 ? 1 : (okf32 ? 3 : (okbf ? 2 : 0));

        size_t g = (size_t)(blockIdx.x - TOK) * 256 + tid;
        float f[16];
        if (mode == 0) {
            int8_t b[16];
            *(int4*)b = ((const int4*)w)[g];
#pragma unroll
            for (int j = 0; j < 16; j++) f[j] = (float)b[j];
        } else if (mode == 1) {
            const int4* wi = (const int4*)w + g * 4;
#pragma unroll
            for (int j = 0; j < 4; j++) {
                int4 v = wi[j];
                f[j * 4 + 0] = (float)(int8_t)v.x; f[j * 4 + 1] = (float)(int8_t)v.y;
                f[j * 4 + 2] = (float)(int8_t)v.z; f[j * 4 + 3] = (float)(int8_t)v.w;
            }
        } else if (mode == 2) {
            const __nv_bfloat16* wb = (const __nv_bfloat16*)w + g * 16;
#pragma unroll
            for (int j = 0; j < 16; j++) f[j] = __bfloat162float(wb[j]);
        } else {
            const float4* wf = (const float4*)w + g * 4;
#pragma unroll
            for (int j = 0; j < 4; j++) {
                float4 v = wf[j];
                f[j * 4 + 0] = v.x; f[j * 4 + 1] = v.y;
                f[j * 4 + 2] = v.z; f[j * 4 + 3] = v.w;
            }
        }
        uint32_t o[8];
#pragma unroll
        for (int j = 0; j < 8; j++) {
            __nv_bfloat162 h = __floats2bfloat162_rn(f[2 * j], f[2 * j + 1]);
            o[j] = *(uint32_t*)&h;
        }
        uint4* dst = (uint4*)(g_wbf + g * 16);
        dst[0] = make_uint4(o[0], o[1], o[2], o[3]);
        dst[1] = make_uint4(o[4], o[5], o[6], o[7]);
    }
}

// ---------------------------------------------------------------------------
// GEMM: bf16 HMMA, 128x64 tile, 64 thr (2 warps x 64x64), 2-stage,
// XOR-swizzled smem, 4 CTAs/SM
// ---------------------------------------------------------------------------
__device__ __forceinline__ void copy_chunk(const __nv_bfloat16* abase_g,
                                           const __nv_bfloat16* bbase_g,
                                           int c, int stage, uint32_t sb, int tid) {
    uint32_t st = sb + SM_AB + stage * STAGE_BYTES;
    // A: 128 rows x 128 B = 1024 cp16 -> 16 per thread
    const char* asrc = (const char*)abase_g + (size_t)c * KCB;
#pragma unroll
    for (int i = 0; i < 16; i++) {
        int idx = tid + i * 64;
        int row = idx >> 3, u = idx & 7;
        cp16(st + row * ROWB + ((u ^ (row & 7)) * 16),
             asrc + (size_t)row * (KDIM * 2) + u * 16);
    }
    // B: 64 rows x 128 B = 512 cp16 -> 8 per thread
    const char* bsrc = (const char*)bbase_g + (size_t)c * KCB;
    uint32_t bb = st + A_BYTES;
#pragma unroll
    for (int i = 0; i < 8; i++) {
        int idx = tid + i * 64;
        int row = idx >> 3, u = idx & 7;
        cp16(bb + row * ROWB + ((u ^ (row & 7)) * 16),
             bsrc + (size_t)row * (KDIM * 2) + u * 16);
    }
}

__global__ void __launch_bounds__(64, 4) hmma_gemm(const float* __restrict__ wscale,
                                                   const float* __restrict__ bias,
                                                   float* __restrict__ out) {
    extern __shared__ char smem[];
    uint32_t sb = smem_u32(smem);
    int tid = threadIdx.x, wid = tid >> 5, lane = tid & 31;
    int m0 = blockIdx.x * TILE_M;      // x = M (L2 reuse of A)
    int n0 = blockIdx.y * TILE_N;
    int wm = wid;                      // 2 M-strips of 64; warp N = full 64

    float* smem_ws = (float*)(smem + SM_WS);
    float* smem_bs = (float*)(smem + SM_BS);
    smem_ws[tid] = wscale[n0 + tid];   // 64 threads, 64 cols
    smem_bs[tid] = bias[n0 + tid];

    int g = lane >> 3, lr = lane & 7;
    uint32_t arow = (uint32_t)(wm * 64 + (g & 1) * 8 + lr);
    uint32_t aoff = arow * ROWB ^ ((arow & 7) * 16) ^ ((uint32_t)(g >> 1) * 16);
    uint32_t brow = (uint32_t)((g >> 1) * 8 + lr);
    uint32_t boff = (uint32_t)A_BYTES + (brow * ROWB ^ ((brow & 7) * 16) ^ ((uint32_t)(g & 1) * 16));

    float acc[4][8][4];
#pragma unroll
    for (int f = 0; f < 4; f++)
#pragma unroll
        for (int nf = 0; nf < 8; nf++)
#pragma unroll
            for (int i = 0; i < 4; i++) acc[f][nf][i] = 0.0f;

    const __nv_bfloat16* Ag = g_xbf + (size_t)m0 * KDIM;
    const __nv_bfloat16* Bg = g_wbf + (size_t)n0 * KDIM;

    copy_chunk(Ag, Bg, 0, 0, sb, tid);
    asm volatile("cp.async.commit_group;" ::: "memory");

    for (int c = 0; c < NCH; c++) {
        asm volatile("cp.async.wait_group 0;" ::: "memory");   // own chunk c done
        __syncthreads();          // cross-thread visibility + both warps off c-1
        if (c + 1 < NCH) {
            copy_chunk(Ag, Bg, c + 1, (c + 1) & 1, sb, tid);
            asm volatile("cp.async.commit_group;" ::: "memory");
        }

        uint32_t st = sb + SM_AB + (c & 1) * STAGE_BYTES;
#pragma unroll
        for (int ks = 0; ks < 4; ks++) {      // 4 x k16 (32 B) per 128-B chunk
            uint32_t kpart = (uint32_t)(ks * 32);
            uint32_t a[4][4];
#pragma unroll
            for (int f = 0; f < 4; f++)
                ldsm_x4(a[f], st + f * (16 * ROWB) + (aoff ^ kpart));
            uint32_t b[4][4];
#pragma unroll
            for (int q = 0; q < 4; q++)
                ldsm_x4(b[q], st + q * (16 * ROWB) + (boff ^ kpart));
#pragma unroll
            for (int f = 0; f < 4; f++)
#pragma unroll
                for (int q = 0; q < 4; q++) {
                    mma_bf16_k16(acc[f][2 * q],     a[f], b[q][0], b[q][1]);
                    mma_bf16_k16(acc[f][2 * q + 1], a[f], b[q][2], b[q][3]);
                }
        }
    }

    int lrow = lane >> 2, lcol2 = (lane & 3) * 2;
#pragma unroll
    for (int f = 0; f < 4; f++) {
        int mA = m0 + wm * 64 + f * 16 + lrow;
        float as0 = g_ascale[mA];
        float as1 = g_ascale[mA + 8];
#pragma unroll
        for (int nf = 0; nf < 8; nf++) {
            int col = nf * 8 + lcol2;
            float ws0 = smem_ws[col], ws1 = smem_ws[col + 1];
            float bs0 = smem_bs[col], bs1 = smem_bs[col + 1];
            float2 v0, v1;
            v0.x = fmaf(acc[f][nf][0] * as0, ws0, bs0);
            v0.y = fmaf(acc[f][nf][1] * as0, ws1, bs1);
            v1.x = fmaf(acc[f][nf][2] * as1, ws0, bs0);
            v1.y = fmaf(acc[f][nf][3] * as1, ws1, bs1);
            *(float2*)(out + (size_t)mA * NDIM + n0 + col) = v0;
            *(float2*)(out + (size_t)(mA + 8) * NDIM + n0 + col) = v1;
        }
    }
}

// ---------------------------------------------------------------------------
extern "C" void kernel_launch(void* const* d_in, const int* in_sizes, int n_in,
                              void* d_out, int out_size) {
    const float* x;
    const float* bs;
    if (in_sizes[0] == NDIM) {           // alphabetical: bias first
        bs = (const float*)d_in[0];
        x  = (const float*)d_in[3];
    } else {                             // dict order: x first
        x  = (const float*)d_in[0];
        bs = (const float*)d_in[3];
    }
    const void*  w  = d_in[1];
    const float* ws = (const float*)d_in[2];
    float* out = (float*)d_out;

    cudaFuncSetAttribute(hmma_gemm, cudaFuncAttributeMaxDynamicSharedMemorySize, SMEM_TOTAL);

    prep_kernel<<<PREP_GRID, 256>>>(x, w);
    dim3 grid(TOK / TILE_M, NDIM / TILE_N);   // (32, 192)
    hmma_gemm<<<grid, 64, SMEM_TOTAL>>>(ws, bs, out);
}